// round 4
// baseline (speedup 1.0000x reference)
#include <cuda_runtime.h>

// PatchEmbedding: x(1,3,384,384) f32, W(768,12), b(768), positions(768,146689)
// out[e,l] = b[e] + positions[e,l] + sum_d patch[d,l] * W[e,d]
// Packed f32x2 version: each thread computes l and l+TPB together in 64-bit
// packed registers (FFMA2 / fma.rn.f32x2, sm_103a).

#define IMG      384
#define LW       383
#define L_TOTAL  (383 * 383)         // 146689
#define EMB      768
#define PD       12

#define TPB      256
#define LPT      2                   // packed pair: l and l+TPB
#define L_TILE   (TPB * LPT)         // 512
#define E_TILE   64                  // 768/64 = 12 y-blocks
#define CH       4                   // ee per prefetch chunk (8 LDGs in flight)
#define NCH      (E_TILE / CH)       // 16

typedef unsigned long long ull;

__device__ __forceinline__ ull mul2(ull a, ull b) {
    ull d; asm("mul.rn.f32x2 %0, %1, %2;" : "=l"(d) : "l"(a), "l"(b)); return d;
}
__device__ __forceinline__ ull fma2(ull a, ull b, ull c) {
    ull d; asm("fma.rn.f32x2 %0, %1, %2, %3;" : "=l"(d) : "l"(a), "l"(b), "l"(c)); return d;
}
__device__ __forceinline__ ull add2(ull a, ull b) {
    ull d; asm("add.rn.f32x2 %0, %1, %2;" : "=l"(d) : "l"(a), "l"(b)); return d;
}
__device__ __forceinline__ ull pack2(float lo, float hi) {
    ull r; asm("mov.b64 %0, {%1, %2};" : "=l"(r) : "f"(lo), "f"(hi)); return r;
}
__device__ __forceinline__ void unpack2(ull v, float& lo, float& hi) {
    asm("mov.b64 {%0, %1}, %2;" : "=f"(lo), "=f"(hi) : "l"(v));
}

__device__ __forceinline__ void gather_patch(const float* __restrict__ x,
                                             int l, float* p) {
    const int r   = l / LW;
    const int col = l - r * LW;
    const float* xp = x + r * IMG + col;
    #pragma unroll
    for (int c = 0; c < 3; c++)
        #pragma unroll
        for (int i = 0; i < 2; i++)
            #pragma unroll
            for (int j = 0; j < 2; j++)
                p[c * 4 + i * 2 + j] = xp[c * IMG * IMG + i * IMG + j];
}

__global__ __launch_bounds__(TPB, 4)
void patch_embed_kernel(const float* __restrict__ x,
                        const float* __restrict__ W,
                        const float* __restrict__ b,
                        const float* __restrict__ pos,
                        float* __restrict__ out) {
    // W duplicated as {w,w} pairs: 12 pairs (96B) per ee row, 16B-aligned.
    __shared__ __align__(16) float2 sW2[E_TILE * PD];   // 6 KB
    __shared__ __align__(8)  float2 sB2[E_TILE];        // 512 B

    const int e0 = blockIdx.y * E_TILE;

    for (int i = threadIdx.x; i < E_TILE * PD; i += TPB) {
        const float w = W[(size_t)e0 * PD + i];
        sW2[i] = make_float2(w, w);
    }
    if (threadIdx.x < E_TILE) {
        const float bv = b[e0 + threadIdx.x];
        sB2[threadIdx.x] = make_float2(bv, bv);
    }

    const int lbase = blockIdx.x * L_TILE + threadIdx.x;
    const bool full_block = (blockIdx.x + 1) * L_TILE <= L_TOTAL;

    if (full_block) {
        // ---- fast path ----
        float pa[PD], pb[PD];
        gather_patch(x, lbase, pa);
        gather_patch(x, lbase + TPB, pb);
        ull p2[PD];
        #pragma unroll
        for (int d = 0; d < PD; d++)
            p2[d] = pack2(pa[d], pb[d]);

        __syncthreads();

        const float* __restrict__ posrow = pos + (size_t)e0 * L_TOTAL + lbase;
        float*       __restrict__ outrow = out + (size_t)e0 * L_TOTAL + lbase;

        const ulonglong2* __restrict__ sWv = (const ulonglong2*)sW2;  // 6 per ee
        const ull* __restrict__ sBv = (const ull*)sB2;

        // Double-buffered prefetch: 8 independent pos loads in flight.
        ull pv[2][CH];

        #pragma unroll
        for (int j = 0; j < CH; j++)
            pv[0][j] = pack2(posrow[j * L_TOTAL],
                             posrow[j * L_TOTAL + TPB]);

        #pragma unroll 2
        for (int cc = 0; cc < NCH; cc++) {
            const int cur = cc & 1;

            if (cc + 1 < NCH) {
                const int eb = (cc + 1) * CH;
                #pragma unroll
                for (int j = 0; j < CH; j++)
                    pv[cur ^ 1][j] = pack2(posrow[(eb + j) * L_TOTAL],
                                           posrow[(eb + j) * L_TOTAL + TPB]);
            }

            #pragma unroll
            for (int j = 0; j < CH; j++) {
                const int ee = cc * CH + j;
                const ulonglong2 w01 = sWv[ee * 6 + 0];
                const ulonglong2 w23 = sWv[ee * 6 + 1];
                const ulonglong2 w45 = sWv[ee * 6 + 2];
                const ulonglong2 w67 = sWv[ee * 6 + 3];
                const ulonglong2 w89 = sWv[ee * 6 + 4];
                const ulonglong2 wAB = sWv[ee * 6 + 5];

                // Two depth-6 packed chains.
                ull ca = mul2(p2[0], w01.x);
                ull cb = mul2(p2[1], w01.y);
                ca = fma2(p2[2],  w23.x, ca);  cb = fma2(p2[3],  w23.y, cb);
                ca = fma2(p2[4],  w45.x, ca);  cb = fma2(p2[5],  w45.y, cb);
                ca = fma2(p2[6],  w67.x, ca);  cb = fma2(p2[7],  w67.y, cb);
                ca = fma2(p2[8],  w89.x, ca);  cb = fma2(p2[9],  w89.y, cb);
                ca = fma2(p2[10], wAB.x, ca);  cb = fma2(p2[11], wAB.y, cb);

                ull s = add2(add2(ca, cb), add2(sBv[ee], pv[cur][j]));

                float o0, o1;
                unpack2(s, o0, o1);
                outrow[ee * L_TOTAL]       = o0;
                outrow[ee * L_TOTAL + TPB] = o1;
            }
        }
    } else {
        // ---- masked tail path (1 of 287 l-blocks) ----
        float p[LPT][PD];
        bool  valid[LPT];
        #pragma unroll
        for (int k = 0; k < LPT; k++) {
            const int l = lbase + k * TPB;
            valid[k] = (l < L_TOTAL);
            gather_patch(x, valid[k] ? l : 0, p[k]);
        }

        __syncthreads();

        const float* __restrict__ posrow = pos + (size_t)e0 * L_TOTAL + lbase;
        float*       __restrict__ outrow = out + (size_t)e0 * L_TOTAL + lbase;

        for (int ee = 0; ee < E_TILE; ee++) {
            const float bb = sB2[ee].x;
            float wv[PD];
            #pragma unroll
            for (int d = 0; d < PD; d++)
                wv[d] = sW2[ee * PD + d].x;
            #pragma unroll
            for (int k = 0; k < LPT; k++) {
                if (valid[k]) {
                    float c0 = p[k][0] * wv[0];
                    float c1 = p[k][1] * wv[1];
                    #pragma unroll
                    for (int d = 2; d < PD; d += 2) {
                        c0 = fmaf(p[k][d],     wv[d],     c0);
                        c1 = fmaf(p[k][d + 1], wv[d + 1], c1);
                    }
                    const float pvv = posrow[ee * L_TOTAL + k * TPB];
                    outrow[ee * L_TOTAL + k * TPB] = (bb + pvv) + (c0 + c1);
                }
            }
        }
    }
}

extern "C" void kernel_launch(void* const* d_in, const int* in_sizes, int n_in,
                              void* d_out, int out_size) {
    const float* x   = (const float*)d_in[0];
    const float* W   = (const float*)d_in[1];
    const float* b   = (const float*)d_in[2];
    const float* pos = (const float*)d_in[3];
    float* out = (float*)d_out;

    dim3 grid((L_TOTAL + L_TILE - 1) / L_TILE,   // 287
              EMB / E_TILE,                      // 12
              1);
    patch_embed_kernel<<<grid, TPB>>>(x, W, b, pos, out);
}

// round 5
// speedup vs baseline: 1.2500x; 1.2500x over previous
#include <cuda_runtime.h>

// PatchEmbedding: x(1,3,384,384) f32, W(768,12), b(768), positions(768,146689)
// out[e,l] = b[e] + positions[e,l] + sum_d patch[d,l] * W[e,d]
// d = c*4 + i*2 + j, l = r*383 + col, patch value = x[c, r+i, col+j]

#define IMG      384
#define LW       383
#define L_TOTAL  (383 * 383)         // 146689
#define EMB      768
#define PD       12

#define TPB      256
#define E_TILE   64                  // 768/64 = 12 y-blocks
#define CH       8                   // ee per prefetch chunk (8 LDGs in flight)
#define NCH      (E_TILE / CH)       // 8

__device__ __forceinline__ void gather_patch(const float* __restrict__ x,
                                             int l, float* p) {
    const int r   = l / LW;
    const int col = l - r * LW;
    const float* xp = x + r * IMG + col;
    #pragma unroll
    for (int c = 0; c < 3; c++)
        #pragma unroll
        for (int i = 0; i < 2; i++)
            #pragma unroll
            for (int j = 0; j < 2; j++)
                p[c * 4 + i * 2 + j] = xp[c * IMG * IMG + i * IMG + j];
}

__device__ __forceinline__ float dot12(const float* p,
                                       float4 w0, float4 w1, float4 w2) {
    // Two depth-6 chains.
    float c0 = p[0] * w0.x;
    float c1 = p[1] * w0.y;
    c0 = fmaf(p[2],  w0.z, c0);  c1 = fmaf(p[3],  w0.w, c1);
    c0 = fmaf(p[4],  w1.x, c0);  c1 = fmaf(p[5],  w1.y, c1);
    c0 = fmaf(p[6],  w1.z, c0);  c1 = fmaf(p[7],  w1.w, c1);
    c0 = fmaf(p[8],  w2.x, c0);  c1 = fmaf(p[9],  w2.y, c1);
    c0 = fmaf(p[10], w2.z, c0);  c1 = fmaf(p[11], w2.w, c1);
    return c0 + c1;
}

__global__ __launch_bounds__(TPB, 5)   // ~48 regs -> 40 warps/SM
void patch_embed_kernel(const float* __restrict__ x,
                        const float* __restrict__ W,
                        const float* __restrict__ b,
                        const float* __restrict__ pos,
                        float* __restrict__ out) {
    __shared__ float4 sW[E_TILE * 3];
    __shared__ float  sB[E_TILE];

    const int e0 = blockIdx.y * E_TILE;

    {
        const float4* Wg = (const float4*)(W + (size_t)e0 * PD);
        for (int i = threadIdx.x; i < E_TILE * 3; i += TPB)
            sW[i] = Wg[i];
        if (threadIdx.x < E_TILE)
            sB[threadIdx.x] = b[e0 + threadIdx.x];
    }

    const int  lbase = blockIdx.x * TPB + threadIdx.x;
    const bool valid = (lbase < L_TOTAL);

    // Gather this thread's single patch vector once (x stays L2/L1-hot;
    // amortized over E_TILE e-rows).
    float p[PD];
    gather_patch(x, valid ? lbase : 0, p);

    __syncthreads();

    if (!valid) return;   // only sub-warp of the final x-block

    const float* __restrict__ posrow = pos + (size_t)e0 * L_TOTAL + lbase;
    float*       __restrict__ outrow = out + (size_t)e0 * L_TOTAL + lbase;

    // Double-buffered prefetch: 8 independent streaming pos loads in flight,
    // compute window per chunk is half of R3's -> higher HBM duty cycle.
    float pv[2][CH];

    #pragma unroll
    for (int j = 0; j < CH; j++)
        pv[0][j] = __ldcs(posrow + j * L_TOTAL);

    #pragma unroll
    for (int cc = 0; cc < NCH; cc++) {
        const int cur = cc & 1;

        if (cc + 1 < NCH) {
            const int eb = (cc + 1) * CH;
            #pragma unroll
            for (int j = 0; j < CH; j++)
                pv[cur ^ 1][j] = __ldcs(posrow + (size_t)(eb + j) * L_TOTAL);
        }

        #pragma unroll
        for (int j = 0; j < CH; j++) {
            const int ee = cc * CH + j;
            const float4 w0 = sW[ee * 3 + 0];
            const float4 w1 = sW[ee * 3 + 1];
            const float4 w2 = sW[ee * 3 + 2];
            const float  bb = sB[ee];
            const float  d  = dot12(p, w0, w1, w2);
            __stcs(outrow + (size_t)ee * L_TOTAL, (bb + pv[cur][j]) + d);
        }
    }
}

extern "C" void kernel_launch(void* const* d_in, const int* in_sizes, int n_in,
                              void* d_out, int out_size) {
    const float* x   = (const float*)d_in[0];
    const float* W   = (const float*)d_in[1];
    const float* b   = (const float*)d_in[2];
    const float* pos = (const float*)d_in[3];
    float* out = (float*)d_out;

    dim3 grid((L_TOTAL + TPB - 1) / TPB,   // 574
              EMB / E_TILE,                // 12
              1);
    patch_embed_kernel<<<grid, TPB>>>(x, W, b, pos, out);
}

// round 6
// speedup vs baseline: 1.2646x; 1.0117x over previous
#include <cuda_runtime.h>

// PatchEmbedding: x(1,3,384,384) f32, W(768,12), b(768), positions(768,146689)
// out[e,l] = b[e] + positions[e,l] + sum_d patch[d,l] * W[e,d]
// d = c*4 + i*2 + j, l = r*383 + col, patch value = x[c, r+i, col+j]
//
// W/b in __constant__: warp-uniform indexing -> LDCU on the uniform path,
// keeping the L1tex pipe exclusively for the compulsory pos-LDG / out-STG.

#define IMG      384
#define LW       383
#define L_TOTAL  (383 * 383)         // 146689
#define EMB      768
#define PD       12

#define TPB      256
#define E_TILE   64                  // 768/64 = 12 y-blocks
#define CH       8                   // ee per prefetch chunk (8 LDGs in flight)
#define NCH      (E_TILE / CH)       // 8

__constant__ float cW[EMB * PD];     // 36 KB
__constant__ float cB[EMB];          // 3 KB

__device__ __forceinline__ void gather_patch(const float* __restrict__ x,
                                             int l, float* p) {
    const int r   = l / LW;
    const int col = l - r * LW;
    const float* xp = x + r * IMG + col;
    #pragma unroll
    for (int c = 0; c < 3; c++)
        #pragma unroll
        for (int i = 0; i < 2; i++)
            #pragma unroll
            for (int j = 0; j < 2; j++)
                p[c * 4 + i * 2 + j] = xp[c * IMG * IMG + i * IMG + j];
}

__device__ __forceinline__ float dot12c(const float* p, int e) {
    const float* w = cW + e * PD;    // warp-uniform -> LDCU
    // Two depth-6 chains.
    float c0 = p[0] * w[0];
    float c1 = p[1] * w[1];
    c0 = fmaf(p[2],  w[2],  c0);  c1 = fmaf(p[3],  w[3],  c1);
    c0 = fmaf(p[4],  w[4],  c0);  c1 = fmaf(p[5],  w[5],  c1);
    c0 = fmaf(p[6],  w[6],  c0);  c1 = fmaf(p[7],  w[7],  c1);
    c0 = fmaf(p[8],  w[8],  c0);  c1 = fmaf(p[9],  w[9],  c1);
    c0 = fmaf(p[10], w[10], c0);  c1 = fmaf(p[11], w[11], c1);
    return c0 + c1;
}

__global__ __launch_bounds__(TPB, 6)   // no smem; target 42 regs -> 48 warps/SM
void patch_embed_kernel(const float* __restrict__ x,
                        const float* __restrict__ pos,
                        float* __restrict__ out) {
    const int e0    = blockIdx.y * E_TILE;
    const int lbase = blockIdx.x * TPB + threadIdx.x;
    if (lbase >= L_TOTAL) return;     // only a sub-warp of the last x-block

    // Gather the 12-element patch once (x is 1.7MB -> L2-hot; reused E_TILE x).
    float p[PD];
    gather_patch(x, lbase, p);

    const float* __restrict__ posrow = pos + (size_t)e0 * L_TOTAL + lbase;
    float*       __restrict__ outrow = out + (size_t)e0 * L_TOTAL + lbase;

    // Double-buffered prefetch: 8 independent streaming pos loads in flight.
    float pv[2][CH];

    #pragma unroll
    for (int j = 0; j < CH; j++)
        pv[0][j] = __ldcs(posrow + (size_t)j * L_TOTAL);

    #pragma unroll
    for (int cc = 0; cc < NCH; cc++) {
        const int cur = cc & 1;

        if (cc + 1 < NCH) {
            const int eb = (cc + 1) * CH;
            #pragma unroll
            for (int j = 0; j < CH; j++)
                pv[cur ^ 1][j] = __ldcs(posrow + (size_t)(eb + j) * L_TOTAL);
        }

        #pragma unroll
        for (int j = 0; j < CH; j++) {
            const int ee = cc * CH + j;
            const float d = dot12c(p, e0 + ee);
            __stcs(outrow + (size_t)ee * L_TOTAL,
                   (cB[e0 + ee] + pv[cur][j]) + d);
        }
    }
}

extern "C" void kernel_launch(void* const* d_in, const int* in_sizes, int n_in,
                              void* d_out, int out_size) {
    const float* x   = (const float*)d_in[0];
    const float* W   = (const float*)d_in[1];
    const float* b   = (const float*)d_in[2];
    const float* pos = (const float*)d_in[3];
    float* out = (float*)d_out;

    // D2D async copies into constant bank (graph-capturable memcpy nodes).
    cudaMemcpyToSymbolAsync(cW, W, EMB * PD * sizeof(float), 0,
                            cudaMemcpyDeviceToDevice);
    cudaMemcpyToSymbolAsync(cB, b, EMB * sizeof(float), 0,
                            cudaMemcpyDeviceToDevice);

    dim3 grid((L_TOTAL + TPB - 1) / TPB,   // 574
              EMB / E_TILE,                // 12
              1);
    patch_embed_kernel<<<grid, TPB>>>(x, pos, out);
}